// round 1
// baseline (speedup 1.0000x reference)
#include <cuda_runtime.h>
#include <math.h>

// Problem constants
#define BB   2
#define SS_  4096
#define DD   512
#define HH   8
#define DEP  64
#define BH   16            // BB*HH
#define MM   8192          // BB*SS_

// Scratch (static device globals; allocation-free contract)
__device__ float g_qh[BH * SS_ * DEP];   // [bh][s][d]
__device__ float g_kh[BH * SS_ * DEP];
__device__ float g_vh[BH * SS_ * DEP];
__device__ float g_ctx[MM * DD];         // [b*s][h*64+d]
__device__ float g_inv[BH * SS_];        // 1/rowsum

// ---------------------------------------------------------------------------
// GEMM: Y(8192x512) = X(8192x512) @ W(512x512) + bias
// MODE 0: Y row-major [m][n]
// MODE 1: head-split layout Y[((b*8+h)*4096 + s)*64 + d], h == blockIdx.x
// BM=128, BN=64, BK=16, 256 threads, 8x4 microtile
// ---------------------------------------------------------------------------
template <int MODE>
__global__ void __launch_bounds__(256)
gemm512(const float* __restrict__ X, const float* __restrict__ W,
        const float* __restrict__ bias, float* __restrict__ Y) {
    __shared__ float Xts[16][132];  // [k][m] transposed, padded
    __shared__ float Ws[16][68];    // [k][n]

    const int tid = threadIdx.x;
    const int tx = tid & 15, ty = tid >> 4;
    const int n0 = blockIdx.x * 64;
    const int m0 = blockIdx.y * 128;

    float acc[8][4];
#pragma unroll
    for (int r = 0; r < 8; r++)
#pragma unroll
        for (int c = 0; c < 4; c++) acc[r][c] = 0.f;

    const int xrow = tid >> 1;
    const int xkb  = (tid & 1) * 8;
    const int wkk  = tid >> 4;
    const int wnb  = (tid & 15) * 4;

    for (int k0 = 0; k0 < 512; k0 += 16) {
        float4 xa = *(const float4*)&X[(size_t)(m0 + xrow) * 512 + k0 + xkb];
        float4 xb = *(const float4*)&X[(size_t)(m0 + xrow) * 512 + k0 + xkb + 4];
        Xts[xkb + 0][xrow] = xa.x; Xts[xkb + 1][xrow] = xa.y;
        Xts[xkb + 2][xrow] = xa.z; Xts[xkb + 3][xrow] = xa.w;
        Xts[xkb + 4][xrow] = xb.x; Xts[xkb + 5][xrow] = xb.y;
        Xts[xkb + 6][xrow] = xb.z; Xts[xkb + 7][xrow] = xb.w;
        *(float4*)&Ws[wkk][wnb] =
            *(const float4*)&W[(size_t)(k0 + wkk) * 512 + n0 + wnb];
        __syncthreads();
#pragma unroll
        for (int kk = 0; kk < 16; kk++) {
            float a[8], b[4];
            *(float4*)&a[0] = *(float4*)&Xts[kk][ty * 8];
            *(float4*)&a[4] = *(float4*)&Xts[kk][ty * 8 + 4];
            *(float4*)&b[0] = *(float4*)&Ws[kk][tx * 4];
#pragma unroll
            for (int r = 0; r < 8; r++)
#pragma unroll
                for (int c = 0; c < 4; c++) acc[r][c] += a[r] * b[c];
        }
        __syncthreads();
    }

    float bv[4];
    *(float4*)&bv[0] = *(const float4*)&bias[n0 + tx * 4];

#pragma unroll
    for (int r = 0; r < 8; r++) {
        const int m = m0 + ty * 8 + r;
        float4 o;
        o.x = acc[r][0] + bv[0]; o.y = acc[r][1] + bv[1];
        o.z = acc[r][2] + bv[2]; o.w = acc[r][3] + bv[3];
        if (MODE == 0) {
            *(float4*)&Y[(size_t)m * 512 + n0 + tx * 4] = o;
        } else {
            const int b = m >> 12, s = m & 4095;
            const int h = blockIdx.x;  // BN==64==DEP so one head per block col
            *(float4*)&Y[(((size_t)(b * 8 + h)) * SS_ + s) * DEP + tx * 4] = o;
        }
    }
}

// ---------------------------------------------------------------------------
// Causal attention, one pass:
//   S = Qh Kh^T / 8 ; P = exp(S) masked ; attn_out <- P (unnormalized)
//   ctx <- (P V) / rowsum ; g_inv <- 1/rowsum
// Block: 128 rows x full causal width, col tiles of 64. 256 threads.
// ---------------------------------------------------------------------------
__global__ void __launch_bounds__(256)
attn_kernel(float* __restrict__ attn_out, int write_attn) {
    extern __shared__ float sm[];
    float* Qts = sm;            // [64][132]  (d-major)
    float* Kts = sm + 8448;     // [64][68]   (d-major)
    float* Vs  = sm + 12800;    // [64][68]   (j-major)
    float* Pts = sm + 17152;    // [64][132]  (j-major, transposed P)
    float* red = sm + 25600;    // [16][128]

    const int tid = threadIdx.x;
    const int tx = tid & 15, ty = tid >> 4;
    const int rt = 31 - blockIdx.x;      // heavy blocks first
    const int bh = blockIdx.y;
    const int row0 = rt * 128;

    const float* __restrict__ Qh = g_qh + (size_t)bh * SS_ * DEP;
    const float* __restrict__ Kh = g_kh + (size_t)bh * SS_ * DEP;
    const float* __restrict__ Vh = g_vh + (size_t)bh * SS_ * DEP;

    // Load Q tile transposed: Qts[d][row]
    {
        const int qrow = tid >> 1;
        const int qdb  = (tid & 1) * 32;
#pragma unroll
        for (int i = 0; i < 8; i++) {
            float4 v = *(const float4*)&Qh[(size_t)(row0 + qrow) * DEP + qdb + i * 4];
            Qts[(qdb + i * 4 + 0) * 132 + qrow] = v.x;
            Qts[(qdb + i * 4 + 1) * 132 + qrow] = v.y;
            Qts[(qdb + i * 4 + 2) * 132 + qrow] = v.z;
            Qts[(qdb + i * 4 + 3) * 132 + qrow] = v.w;
        }
    }

    float ctx[8][4];
    float rs[8];
#pragma unroll
    for (int r = 0; r < 8; r++) {
        rs[r] = 0.f;
#pragma unroll
        for (int c = 0; c < 4; c++) ctx[r][c] = 0.f;
    }

    const int ctmax = 2 * rt + 1;
    const int kr  = tid >> 2;
    const int kdb = (tid & 3) * 16;

    for (int ct = 0; ct <= ctmax; ct++) {
        __syncthreads();  // protect Kts/Vs/Pts from previous iteration readers
        // Load K (transposed) and V (natural)
#pragma unroll
        for (int i = 0; i < 4; i++) {
            float4 kv = *(const float4*)&Kh[(size_t)(ct * 64 + kr) * DEP + kdb + i * 4];
            Kts[(kdb + i * 4 + 0) * 68 + kr] = kv.x;
            Kts[(kdb + i * 4 + 1) * 68 + kr] = kv.y;
            Kts[(kdb + i * 4 + 2) * 68 + kr] = kv.z;
            Kts[(kdb + i * 4 + 3) * 68 + kr] = kv.w;
            float4 vv = *(const float4*)&Vh[(size_t)(ct * 64 + kr) * DEP + kdb + i * 4];
            *(float4*)&Vs[kr * 68 + kdb + i * 4] = vv;
        }
        __syncthreads();

        // GEMM1: S = Q K^T
        float sacc[8][4];
#pragma unroll
        for (int r = 0; r < 8; r++)
#pragma unroll
            for (int c = 0; c < 4; c++) sacc[r][c] = 0.f;
#pragma unroll 8
        for (int kk = 0; kk < 64; kk++) {
            float a[8], b[4];
            *(float4*)&a[0] = *(float4*)&Qts[kk * 132 + ty * 8];
            *(float4*)&a[4] = *(float4*)&Qts[kk * 132 + ty * 8 + 4];
            *(float4*)&b[0] = *(float4*)&Kts[kk * 68 + tx * 4];
#pragma unroll
            for (int r = 0; r < 8; r++)
#pragma unroll
                for (int c = 0; c < 4; c++) sacc[r][c] += a[r] * b[c];
        }

        // exp + causal mask, write unnormalized P to attn, stage P^T in smem
#pragma unroll
        for (int r = 0; r < 8; r++) {
            const int gi = row0 + ty * 8 + r;
            float p[4];
#pragma unroll
            for (int c = 0; c < 4; c++) {
                const int gj = ct * 64 + tx * 4 + c;
                float e = (gj <= gi) ? __expf(sacc[r][c] * 0.125f) : 0.f;
                p[c] = e;
                rs[r] += e;
            }
            if (write_attn) {
                *(float4*)&attn_out[((size_t)bh * SS_ + gi) * SS_ + ct * 64 + tx * 4] =
                    *(float4*)p;
            }
            Pts[(tx * 4 + 0) * 132 + ty * 8 + r] = p[0];
            Pts[(tx * 4 + 1) * 132 + ty * 8 + r] = p[1];
            Pts[(tx * 4 + 2) * 132 + ty * 8 + r] = p[2];
            Pts[(tx * 4 + 3) * 132 + ty * 8 + r] = p[3];
        }
        __syncthreads();

        // GEMM2: ctx += P V
#pragma unroll 8
        for (int j = 0; j < 64; j++) {
            float a[8], b[4];
            *(float4*)&a[0] = *(float4*)&Pts[j * 132 + ty * 8];
            *(float4*)&a[4] = *(float4*)&Pts[j * 132 + ty * 8 + 4];
            *(float4*)&b[0] = *(float4*)&Vs[j * 68 + tx * 4];
#pragma unroll
            for (int r = 0; r < 8; r++)
#pragma unroll
                for (int c = 0; c < 4; c++) ctx[r][c] += a[r] * b[c];
        }
    }

    // Row-sum reduction across the 16 col-threads
    __syncthreads();
#pragma unroll
    for (int r = 0; r < 8; r++) red[tx * 128 + ty * 8 + r] = rs[r];
    __syncthreads();
    float* rowinv = Kts;  // reuse
    if (tid < 128) {
        float s = 0.f;
#pragma unroll
        for (int x = 0; x < 16; x++) s += red[x * 128 + tid];
        const float inv = 1.f / s;
        rowinv[tid] = inv;
        g_inv[(size_t)bh * SS_ + row0 + tid] = inv;
    }
    __syncthreads();

    const int b = bh >> 3, h = bh & 7;
#pragma unroll
    for (int r = 0; r < 8; r++) {
        const int gi = row0 + ty * 8 + r;
        const float inv = rowinv[ty * 8 + r];
        float4 o;
        o.x = ctx[r][0] * inv; o.y = ctx[r][1] * inv;
        o.z = ctx[r][2] * inv; o.w = ctx[r][3] * inv;
        *(float4*)&g_ctx[((size_t)(b * SS_ + gi)) * DD + h * 64 + tx * 4] = o;
    }
}

// ---------------------------------------------------------------------------
// Normalize attn in place: attn[bh][i][j] *= inv[bh][i]; zeros above diagonal.
// One float4 per thread, exact mapping.
// ---------------------------------------------------------------------------
__global__ void __launch_bounds__(256)
normalize_attn(float* __restrict__ attn) {
    const size_t idx = (size_t)blockIdx.x * 256 + threadIdx.x;  // float4 index
    const int j4 = (int)(idx & 1023);
    const int i  = (int)((idx >> 10) & 4095);
    const int bh = (int)(idx >> 22);
    const int j  = j4 * 4;
    float4* p = (float4*)attn + idx;
    if (j > i) {
        *p = make_float4(0.f, 0.f, 0.f, 0.f);
    } else {
        const float inv = g_inv[(size_t)bh * SS_ + i];
        float4 v = *p;
        if (j + 3 <= i) {
            v.x *= inv; v.y *= inv; v.z *= inv; v.w *= inv;
        } else {
            v.x = (j + 0 <= i) ? v.x * inv : 0.f;
            v.y = (j + 1 <= i) ? v.y * inv : 0.f;
            v.z = (j + 2 <= i) ? v.z * inv : 0.f;
            v.w = (j + 3 <= i) ? v.w * inv : 0.f;
        }
        *p = v;
    }
}

// ---------------------------------------------------------------------------
extern "C" void kernel_launch(void* const* d_in, const int* in_sizes, int n_in,
                              void* d_out, int out_size) {
    const float* q  = (const float*)d_in[2];
    const float* k  = (const float*)d_in[0];
    const float* v  = (const float*)d_in[1];
    const float* Wq = (const float*)d_in[4];
    const float* bq = (const float*)d_in[5];
    const float* Wk = (const float*)d_in[6];
    const float* bk = (const float*)d_in[7];
    const float* Wv = (const float*)d_in[8];
    const float* bv = (const float*)d_in[9];
    const float* Wo = (const float*)d_in[10];
    const float* bo = (const float*)d_in[11];

    float* out = (float*)d_out;
    const size_t BSD = (size_t)BB * SS_ * DD;            // 4,194,304
    const size_t ATT = (size_t)BH * SS_ * SS_;           // 268,435,456

    float* out_main = nullptr;
    float* attn_out = nullptr;
    if ((size_t)out_size >= BSD + ATT) {
        out_main = out;
        attn_out = out + BSD;
    } else if ((size_t)out_size >= ATT) {
        attn_out = out;
    } else {
        out_main = out;
    }

    void *pq, *pk, *pv, *pctx;
    cudaGetSymbolAddress(&pq, g_qh);
    cudaGetSymbolAddress(&pk, g_kh);
    cudaGetSymbolAddress(&pv, g_vh);
    cudaGetSymbolAddress(&pctx, g_ctx);

    cudaFuncSetAttribute(attn_kernel,
                         cudaFuncAttributeMaxDynamicSharedMemorySize, 110592);

    dim3 ggrid(8, 64);
    gemm512<1><<<ggrid, 256>>>(q, Wq, bq, (float*)pq);
    gemm512<1><<<ggrid, 256>>>(k, Wk, bk, (float*)pk);
    gemm512<1><<<ggrid, 256>>>(v, Wv, bv, (float*)pv);

    attn_kernel<<<dim3(32, BH), 256, 110592>>>(attn_out, attn_out != nullptr);

    if (attn_out) {
        // 268,435,456 floats = 67,108,864 float4 = 262144 blocks of 256
        normalize_attn<<<262144, 256>>>(attn_out);
    }
    if (out_main) {
        gemm512<0><<<ggrid, 256>>>((const float*)pctx, Wo, bo, out_main);
    }
}

// round 4
// speedup vs baseline: 3.4598x; 3.4598x over previous
#include <cuda_runtime.h>
#include <math.h>

// Problem constants
#define BB   2
#define SS_  4096
#define DD   512
#define HH   8
#define DEP  64
#define BH   16
#define MM   8192

// Scratch
__device__ float g_qh[BH * SS_ * DEP];
__device__ float g_kh[BH * SS_ * DEP];
__device__ float g_vh[BH * SS_ * DEP];
__device__ float g_ctx[MM * DD];
__device__ float g_inv[BH * SS_];

__device__ __forceinline__ unsigned f2tf(float x) {
    unsigned u;
    asm("cvt.rna.tf32.f32 %0, %1;" : "=r"(u) : "f"(x));
    return u;
}

__device__ __forceinline__ void mma_tf32(float* d, const unsigned* a, const unsigned* b) {
    asm volatile(
        "mma.sync.aligned.m16n8k8.row.col.f32.tf32.tf32.f32 "
        "{%0,%1,%2,%3}, {%4,%5,%6,%7}, {%8,%9}, {%0,%1,%2,%3};"
        : "+f"(d[0]), "+f"(d[1]), "+f"(d[2]), "+f"(d[3])
        : "r"(a[0]), "r"(a[1]), "r"(a[2]), "r"(a[3]), "r"(b[0]), "r"(b[1]));
}

// ---------------------------------------------------------------------------
// Projection GEMM: Y(8192x512) = X @ W + bias, tf32 MMA.
// BM=128, BN=128, BK=32. 256 threads, 8 warps (4x2 over M,N), warp tile 32x64.
// MODE 0: row-major out. MODE 1: head-split out [((b*8+h)*4096+s)*64+d].
// ---------------------------------------------------------------------------
template <int MODE>
__global__ void __launch_bounds__(256, 2)
gemm512_mma(const float* __restrict__ X, const float* __restrict__ W,
            const float* __restrict__ bias, float* __restrict__ Y) {
    __shared__ unsigned Xs[128 * 36];   // [m][k], stride 36 (4g+t unique mod 32)
    __shared__ unsigned Ws[32 * 136];   // [k][n], stride 136 (8t+g unique mod 32)

    const int tid = threadIdx.x;
    const int lane = tid & 31, w = tid >> 5;
    const int g = lane >> 2, t = lane & 3;
    const int wm = w & 3, wn = w >> 2;
    const int m0 = blockIdx.y * 128, n0 = blockIdx.x * 128;

    float acc[2][8][4];
#pragma unroll
    for (int mt = 0; mt < 2; mt++)
#pragma unroll
        for (int nt = 0; nt < 8; nt++)
#pragma unroll
            for (int c = 0; c < 4; c++) acc[mt][nt][c] = 0.f;

    const int xr = tid >> 1, xk = (tid & 1) * 16;
    const int wk = tid >> 3, wn0 = (tid & 7) * 16;

    for (int k0 = 0; k0 < 512; k0 += 32) {
        __syncthreads();
#pragma unroll
        for (int i = 0; i < 4; i++) {
            float4 xv = *(const float4*)&X[(size_t)(m0 + xr) * 512 + k0 + xk + i * 4];
            Xs[xr * 36 + xk + i * 4 + 0] = f2tf(xv.x);
            Xs[xr * 36 + xk + i * 4 + 1] = f2tf(xv.y);
            Xs[xr * 36 + xk + i * 4 + 2] = f2tf(xv.z);
            Xs[xr * 36 + xk + i * 4 + 3] = f2tf(xv.w);
            float4 wv = *(const float4*)&W[(size_t)(k0 + wk) * 512 + n0 + wn0 + i * 4];
            Ws[wk * 136 + wn0 + i * 4 + 0] = f2tf(wv.x);
            Ws[wk * 136 + wn0 + i * 4 + 1] = f2tf(wv.y);
            Ws[wk * 136 + wn0 + i * 4 + 2] = f2tf(wv.z);
            Ws[wk * 136 + wn0 + i * 4 + 3] = f2tf(wv.w);
        }
        __syncthreads();
#pragma unroll
        for (int ks = 0; ks < 4; ks++) {
            const int kk = ks * 8;
            unsigned a[2][4];
#pragma unroll
            for (int mt = 0; mt < 2; mt++) {
                const int r0 = wm * 32 + mt * 16;
                a[mt][0] = Xs[(r0 + g) * 36 + kk + t];
                a[mt][1] = Xs[(r0 + g + 8) * 36 + kk + t];
                a[mt][2] = Xs[(r0 + g) * 36 + kk + t + 4];
                a[mt][3] = Xs[(r0 + g + 8) * 36 + kk + t + 4];
            }
#pragma unroll
            for (int nt = 0; nt < 8; nt++) {
                unsigned b[2];
                const int nn = wn * 64 + nt * 8 + g;
                b[0] = Ws[(kk + t) * 136 + nn];
                b[1] = Ws[(kk + t + 4) * 136 + nn];
                mma_tf32(acc[0][nt], a[0], b);
                mma_tf32(acc[1][nt], a[1], b);
            }
        }
    }

#pragma unroll
    for (int nt = 0; nt < 8; nt++) {
        const int colg = n0 + wn * 64 + nt * 8 + 2 * t;
        const float b0 = bias[colg], b1 = bias[colg + 1];
#pragma unroll
        for (int mt = 0; mt < 2; mt++) {
            const int rbase = m0 + wm * 32 + mt * 16;
#pragma unroll
            for (int half = 0; half < 2; half++) {
                const int r = rbase + g + half * 8;
                float2 o;
                o.x = acc[mt][nt][half * 2 + 0] + b0;
                o.y = acc[mt][nt][half * 2 + 1] + b1;
                if (MODE == 0) {
                    *(float2*)&Y[(size_t)r * 512 + colg] = o;
                } else {
                    const int b = r >> 12, s = r & 4095;
                    const int h = colg >> 6, d = colg & 63;
                    *(float2*)&Y[(((size_t)(b * 8 + h)) * SS_ + s) * DEP + d] = o;
                }
            }
        }
    }
}

// ---------------------------------------------------------------------------
// Causal flash-style attention with tf32 MMA.
// Block: 128 rows x (causal width in 64-col tiles). 8 warps, warp owns 16 rows.
// Writes unnormalized P to attn_out, ctx (normalized) to g_ctx, 1/rowsum to g_inv.
// smem: Qs [128][68] (reused as Ps), Ks [64][72], Vs [64][72] => 17920 u32 = 71680 B
// ---------------------------------------------------------------------------
__global__ void __launch_bounds__(256, 2)
attn_kernel(float* __restrict__ attn_out, int write_attn) {
    extern __shared__ unsigned sm[];
    unsigned* Qs = sm;            // [128][68]
    unsigned* Ks = sm + 8704;     // [d=64][j], stride 72 (t*8+g unique mod 32)
    unsigned* Vs = sm + 13312;    // [j=64][d], stride 72 (t*8+g unique mod 32)

    const int tid = threadIdx.x;
    const int lane = tid & 31, w = tid >> 5;
    const int g = lane >> 2, t = lane & 3;
    const int rt = 31 - blockIdx.x;       // heavy blocks first
    const int bh = blockIdx.y;
    const int row0 = rt * 128;

    const float* __restrict__ Qh = g_qh + (size_t)bh * SS_ * DEP;
    const float* __restrict__ Kh = g_kh + (size_t)bh * SS_ * DEP;
    const float* __restrict__ Vh = g_vh + (size_t)bh * SS_ * DEP;

    // Stage Q -> smem (tf32)
    {
        const int qr = tid >> 1, qdb = (tid & 1) * 32;
#pragma unroll
        for (int i = 0; i < 8; i++) {
            float4 v = *(const float4*)&Qh[(size_t)(row0 + qr) * DEP + qdb + i * 4];
            uint4 u;
            u.x = f2tf(v.x); u.y = f2tf(v.y); u.z = f2tf(v.z); u.w = f2tf(v.w);
            *(uint4*)&Qs[qr * 68 + qdb + i * 4] = u;
        }
    }
    __syncthreads();

    // Extract Q fragments (warp's own 16 rows, K=64 -> 8 ksteps)
    unsigned qa[8][4];
    {
        const int rq = w * 16;
#pragma unroll
        for (int ks = 0; ks < 8; ks++) {
            const int kk = ks * 8;
            qa[ks][0] = Qs[(rq + g) * 68 + kk + t];
            qa[ks][1] = Qs[(rq + g + 8) * 68 + kk + t];
            qa[ks][2] = Qs[(rq + g) * 68 + kk + t + 4];
            qa[ks][3] = Qs[(rq + g + 8) * 68 + kk + t + 4];
        }
    }

    float ctx[8][4];
#pragma unroll
    for (int nt = 0; nt < 8; nt++)
#pragma unroll
        for (int c = 0; c < 4; c++) ctx[nt][c] = 0.f;
    float rs0 = 0.f, rs1 = 0.f;

    const int gi0 = row0 + w * 16 + g;
    const int gi1 = gi0 + 8;
    const int jr = tid & 63, jdb = (tid >> 6) * 16;
    const int ctmax = 2 * rt + 1;

    for (int ct = 0; ct <= ctmax; ct++) {
        __syncthreads();  // Ks/Vs safe to overwrite
        // Load K (as [d][j]) and V (as [j][d]), tf32
#pragma unroll
        for (int i = 0; i < 4; i++) {
            float4 kv = *(const float4*)&Kh[(size_t)(ct * 64 + jr) * DEP + jdb + i * 4];
            Ks[(jdb + i * 4 + 0) * 72 + jr] = f2tf(kv.x);
            Ks[(jdb + i * 4 + 1) * 72 + jr] = f2tf(kv.y);
            Ks[(jdb + i * 4 + 2) * 72 + jr] = f2tf(kv.z);
            Ks[(jdb + i * 4 + 3) * 72 + jr] = f2tf(kv.w);
            float4 vv = *(const float4*)&Vh[(size_t)(ct * 64 + jr) * DEP + jdb + i * 4];
            uint4 u;
            u.x = f2tf(vv.x); u.y = f2tf(vv.y); u.z = f2tf(vv.z); u.w = f2tf(vv.w);
            *(uint4*)&Vs[jr * 72 + jdb + i * 4] = u;
        }
        __syncthreads();

        // GEMM1: S = Q K^T (warp 16 x 64)
        float s[8][4];
#pragma unroll
        for (int nt = 0; nt < 8; nt++)
#pragma unroll
            for (int c = 0; c < 4; c++) s[nt][c] = 0.f;
#pragma unroll
        for (int ks = 0; ks < 8; ks++) {
            const int kk = ks * 8;
#pragma unroll
            for (int nt = 0; nt < 8; nt++) {
                unsigned b[2];
                b[0] = Ks[(kk + t) * 72 + nt * 8 + g];
                b[1] = Ks[(kk + t + 4) * 72 + nt * 8 + g];
                mma_tf32(s[nt], qa[ks], b);
            }
        }

        // exp + causal mask; write unnormalized P to gmem; stage tf32(P) in Ps
        unsigned* Ps = Qs;
#pragma unroll
        for (int nt = 0; nt < 8; nt++) {
            const int cj = ct * 64 + nt * 8 + 2 * t;
            float e00 = (cj     <= gi0) ? __expf(s[nt][0] * 0.125f) : 0.f;
            float e01 = (cj + 1 <= gi0) ? __expf(s[nt][1] * 0.125f) : 0.f;
            float e10 = (cj     <= gi1) ? __expf(s[nt][2] * 0.125f) : 0.f;
            float e11 = (cj + 1 <= gi1) ? __expf(s[nt][3] * 0.125f) : 0.f;
            rs0 += e00 + e01;
            rs1 += e10 + e11;
            if (write_attn) {
                float2 p0 = make_float2(e00, e01);
                float2 p1 = make_float2(e10, e11);
                *(float2*)&attn_out[((size_t)bh * SS_ + gi0) * SS_ + cj] = p0;
                *(float2*)&attn_out[((size_t)bh * SS_ + gi1) * SS_ + cj] = p1;
            }
            uint2 u0, u1;
            u0.x = f2tf(e00); u0.y = f2tf(e01);
            u1.x = f2tf(e10); u1.y = f2tf(e11);
            *(uint2*)&Ps[(w * 16 + g) * 68 + nt * 8 + 2 * t] = u0;
            *(uint2*)&Ps[(w * 16 + g + 8) * 68 + nt * 8 + 2 * t] = u1;
        }
        __syncwarp();

        // GEMM2: ctx += P V (warp 16 x 64, k = 64 over j)
#pragma unroll
        for (int js = 0; js < 8; js++) {
            const int jj = js * 8;
            unsigned pa[4];
            pa[0] = Ps[(w * 16 + g) * 68 + jj + t];
            pa[1] = Ps[(w * 16 + g + 8) * 68 + jj + t];
            pa[2] = Ps[(w * 16 + g) * 68 + jj + t + 4];
            pa[3] = Ps[(w * 16 + g + 8) * 68 + jj + t + 4];
#pragma unroll
            for (int nt = 0; nt < 8; nt++) {
                unsigned b[2];
                b[0] = Vs[(jj + t) * 72 + nt * 8 + g];
                b[1] = Vs[(jj + t + 4) * 72 + nt * 8 + g];
                mma_tf32(ctx[nt], pa, b);
            }
        }
        __syncwarp();
    }

    // Row sums (4 lanes per row share t) -> inv
    rs0 += __shfl_xor_sync(0xffffffffu, rs0, 1);
    rs0 += __shfl_xor_sync(0xffffffffu, rs0, 2);
    rs1 += __shfl_xor_sync(0xffffffffu, rs1, 1);
    rs1 += __shfl_xor_sync(0xffffffffu, rs1, 2);
    const float inv0 = 1.f / rs0, inv1 = 1.f / rs1;
    if (t == 0) {
        g_inv[(size_t)bh * SS_ + gi0] = inv0;
        g_inv[(size_t)bh * SS_ + gi1] = inv1;
    }

    // Store normalized ctx
    const int b = bh >> 3, h = bh & 7;
#pragma unroll
    for (int nt = 0; nt < 8; nt++) {
        const int d = nt * 8 + 2 * t;
        float2 o0, o1;
        o0.x = ctx[nt][0] * inv0; o0.y = ctx[nt][1] * inv0;
        o1.x = ctx[nt][2] * inv1; o1.y = ctx[nt][3] * inv1;
        *(float2*)&g_ctx[((size_t)(b * SS_ + gi0)) * DD + h * 64 + d] = o0;
        *(float2*)&g_ctx[((size_t)(b * SS_ + gi1)) * DD + h * 64 + d] = o1;
    }
}

// ---------------------------------------------------------------------------
// Normalize attn in place; zeros above diagonal.
// ---------------------------------------------------------------------------
__global__ void __launch_bounds__(256)
normalize_attn(float* __restrict__ attn) {
    const size_t idx = (size_t)blockIdx.x * 256 + threadIdx.x;  // float4 index
    const int j4 = (int)(idx & 1023);
    const int i  = (int)((idx >> 10) & 4095);
    const int bh = (int)(idx >> 22);
    const int j  = j4 * 4;
    float4* p = (float4*)attn + idx;
    if (j > i) {
        *p = make_float4(0.f, 0.f, 0.f, 0.f);
    } else {
        const float inv = g_inv[(size_t)bh * SS_ + i];
        float4 v = *p;
        if (j + 3 <= i) {
            v.x *= inv; v.y *= inv; v.z *= inv; v.w *= inv;
        } else {
            v.x = (j + 0 <= i) ? v.x * inv : 0.f;
            v.y = (j + 1 <= i) ? v.y * inv : 0.f;
            v.z = (j + 2 <= i) ? v.z * inv : 0.f;
            v.w = (j + 3 <= i) ? v.w * inv : 0.f;
        }
        *p = v;
    }
}

// ---------------------------------------------------------------------------
extern "C" void kernel_launch(void* const* d_in, const int* in_sizes, int n_in,
                              void* d_out, int out_size) {
    const float* q  = (const float*)d_in[2];
    const float* k  = (const float*)d_in[0];
    const float* v  = (const float*)d_in[1];
    const float* Wq = (const float*)d_in[4];
    const float* bq = (const float*)d_in[5];
    const float* Wk = (const float*)d_in[6];
    const float* bk = (const float*)d_in[7];
    const float* Wv = (const float*)d_in[8];
    const float* bv = (const float*)d_in[9];
    const float* Wo = (const float*)d_in[10];
    const float* bo = (const float*)d_in[11];

    float* out = (float*)d_out;
    const size_t BSD = (size_t)BB * SS_ * DD;
    const size_t ATT = (size_t)BH * SS_ * SS_;

    float* out_main = nullptr;
    float* attn_out = nullptr;
    if ((size_t)out_size >= BSD + ATT) {
        out_main = out;
        attn_out = out + BSD;
    } else if ((size_t)out_size >= ATT) {
        attn_out = out;
    } else {
        out_main = out;
    }

    void *pq, *pk, *pv, *pctx;
    cudaGetSymbolAddress(&pq, g_qh);
    cudaGetSymbolAddress(&pk, g_kh);
    cudaGetSymbolAddress(&pv, g_vh);
    cudaGetSymbolAddress(&pctx, g_ctx);

    cudaFuncSetAttribute(attn_kernel,
                         cudaFuncAttributeMaxDynamicSharedMemorySize, 71680);

    dim3 ggrid(4, 64);
    gemm512_mma<1><<<ggrid, 256>>>(q, Wq, bq, (float*)pq);
    gemm512_mma<1><<<ggrid, 256>>>(k, Wk, bk, (float*)pk);
    gemm512_mma<1><<<ggrid, 256>>>(v, Wv, bv, (float*)pv);

    attn_kernel<<<dim3(32, BH), 256, 71680>>>(attn_out, attn_out != nullptr);

    if (attn_out) {
        normalize_attn<<<262144, 256>>>(attn_out);
    }
    if (out_main) {
        gemm512_mma<0><<<ggrid, 256>>>((const float*)pctx, Wo, bo, out_main);
    }
}

// round 8
// speedup vs baseline: 3.8293x; 1.1068x over previous
#include <cuda_runtime.h>
#include <math.h>

// Problem constants
#define BB   2
#define SS_  4096
#define DD   512
#define HH   8
#define DEP  64
#define BH   16
#define MM   8192

// Scratch
__device__ float g_qh[BH * SS_ * DEP];   // tf32-pre-rounded
__device__ float g_kh[BH * SS_ * DEP];   // tf32-pre-rounded
__device__ float g_vh[BH * SS_ * DEP];   // tf32-pre-rounded
__device__ float g_ctx[MM * DD];
__device__ float g_inv[BH * SS_];

__device__ __forceinline__ unsigned f2tf(float x) {
    unsigned u;
    asm("cvt.rna.tf32.f32 %0, %1;" : "=r"(u) : "f"(x));
    return u;
}

__device__ __forceinline__ void mma_tf32(float* d, const unsigned* a, const unsigned* b) {
    asm volatile(
        "mma.sync.aligned.m16n8k8.row.col.f32.tf32.tf32.f32 "
        "{%0,%1,%2,%3}, {%4,%5,%6,%7}, {%8,%9}, {%0,%1,%2,%3};"
        : "+f"(d[0]), "+f"(d[1]), "+f"(d[2]), "+f"(d[3])
        : "r"(a[0]), "r"(a[1]), "r"(a[2]), "r"(a[3]), "r"(b[0]), "r"(b[1]));
}

__device__ __forceinline__ void cp16(unsigned* smem_ptr, const void* gptr) {
    unsigned s = (unsigned)__cvta_generic_to_shared(smem_ptr);
    asm volatile("cp.async.cg.shared.global [%0], [%1], 16;" :: "r"(s), "l"(gptr));
}

// ---------------------------------------------------------------------------
// Projection GEMM: Y(8192x512) = X @ W + bias, tf32 MMA.
// MODE 0: row-major fp32 out. MODE 1: head-split out, tf32-PRE-ROUNDED bits.
// ---------------------------------------------------------------------------
template <int MODE>
__global__ void __launch_bounds__(256, 2)
gemm512_mma(const float* __restrict__ X, const float* __restrict__ W,
            const float* __restrict__ bias, float* __restrict__ Y) {
    __shared__ unsigned Xs[128 * 36];
    __shared__ unsigned Ws[32 * 136];

    const int tid = threadIdx.x;
    const int lane = tid & 31, w = tid >> 5;
    const int g = lane >> 2, t = lane & 3;
    const int wm = w & 3, wn = w >> 2;
    const int m0 = blockIdx.y * 128, n0 = blockIdx.x * 128;

    float acc[2][8][4];
#pragma unroll
    for (int mt = 0; mt < 2; mt++)
#pragma unroll
        for (int nt = 0; nt < 8; nt++)
#pragma unroll
            for (int c = 0; c < 4; c++) acc[mt][nt][c] = 0.f;

    const int xr = tid >> 1, xk = (tid & 1) * 16;
    const int wk = tid >> 3, wn0 = (tid & 7) * 16;

    for (int k0 = 0; k0 < 512; k0 += 32) {
        __syncthreads();
#pragma unroll
        for (int i = 0; i < 4; i++) {
            float4 xv = *(const float4*)&X[(size_t)(m0 + xr) * 512 + k0 + xk + i * 4];
            Xs[xr * 36 + xk + i * 4 + 0] = f2tf(xv.x);
            Xs[xr * 36 + xk + i * 4 + 1] = f2tf(xv.y);
            Xs[xr * 36 + xk + i * 4 + 2] = f2tf(xv.z);
            Xs[xr * 36 + xk + i * 4 + 3] = f2tf(xv.w);
            float4 wv = *(const float4*)&W[(size_t)(k0 + wk) * 512 + n0 + wn0 + i * 4];
            Ws[wk * 136 + wn0 + i * 4 + 0] = f2tf(wv.x);
            Ws[wk * 136 + wn0 + i * 4 + 1] = f2tf(wv.y);
            Ws[wk * 136 + wn0 + i * 4 + 2] = f2tf(wv.z);
            Ws[wk * 136 + wn0 + i * 4 + 3] = f2tf(wv.w);
        }
        __syncthreads();
#pragma unroll
        for (int ks = 0; ks < 4; ks++) {
            const int kk = ks * 8;
            unsigned a[2][4];
#pragma unroll
            for (int mt = 0; mt < 2; mt++) {
                const int r0 = wm * 32 + mt * 16;
                a[mt][0] = Xs[(r0 + g) * 36 + kk + t];
                a[mt][1] = Xs[(r0 + g + 8) * 36 + kk + t];
                a[mt][2] = Xs[(r0 + g) * 36 + kk + t + 4];
                a[mt][3] = Xs[(r0 + g + 8) * 36 + kk + t + 4];
            }
#pragma unroll
            for (int nt = 0; nt < 8; nt++) {
                unsigned b[2];
                const int nn = wn * 64 + nt * 8 + g;
                b[0] = Ws[(kk + t) * 136 + nn];
                b[1] = Ws[(kk + t + 4) * 136 + nn];
                mma_tf32(acc[0][nt], a[0], b);
                mma_tf32(acc[1][nt], a[1], b);
            }
        }
    }

#pragma unroll
    for (int nt = 0; nt < 8; nt++) {
        const int colg = n0 + wn * 64 + nt * 8 + 2 * t;
        const float b0 = bias[colg], b1 = bias[colg + 1];
#pragma unroll
        for (int mt = 0; mt < 2; mt++) {
            const int rbase = m0 + wm * 32 + mt * 16;
#pragma unroll
            for (int half = 0; half < 2; half++) {
                const int r = rbase + g + half * 8;
                float2 o;
                o.x = acc[mt][nt][half * 2 + 0] + b0;
                o.y = acc[mt][nt][half * 2 + 1] + b1;
                if (MODE == 0) {
                    *(float2*)&Y[(size_t)r * 512 + colg] = o;
                } else {
                    o.x = __uint_as_float(f2tf(o.x));
                    o.y = __uint_as_float(f2tf(o.y));
                    const int b = r >> 12, s = r & 4095;
                    const int h = colg >> 6, d = colg & 63;
                    *(float2*)&Y[(((size_t)(b * 8 + h)) * SS_ + s) * DEP + d] = o;
                }
            }
        }
    }
}

// ---------------------------------------------------------------------------
// Causal flash-style attention, tf32 MMA, cp.async double-buffered K/V.
// smem (u32): Qs[128*68]=8704 (reused as Ps), K2[2][64*68]=8704, V2[2][64*72]=9216
//   total 26624 u32 = 106496 B
// ---------------------------------------------------------------------------
__global__ void __launch_bounds__(256, 2)
attn_kernel(float* __restrict__ attn_out, int write_attn) {
    extern __shared__ unsigned sm[];
    unsigned* Qs  = sm;                 // [row][d] stride 68
    unsigned* Kb0 = sm + 8704;          // [j][d] stride 68
    unsigned* Kb1 = sm + 13056;
    unsigned* Vb0 = sm + 17408;         // [j][d] stride 72
    unsigned* Vb1 = sm + 22016;

    const int tid = threadIdx.x;
    const int lane = tid & 31, w = tid >> 5;
    const int g = lane >> 2, t = lane & 3;
    const int rt = 31 - blockIdx.x;     // heavy blocks first
    const int bh = blockIdx.y;
    const int row0 = rt * 128;

    const float* __restrict__ Qh = g_qh + (size_t)bh * SS_ * DEP;
    const float* __restrict__ Kh = g_kh + (size_t)bh * SS_ * DEP;
    const float* __restrict__ Vh = g_vh + (size_t)bh * SS_ * DEP;

    // cp.async mapping for K/V tiles: row = tid>>2 (0..63), 4x16B chunks
    const int kvr = tid >> 2;
    const int kvc = (tid & 3) * 16;

    // Prologue group A: Q tile (128 rows x 64)
    {
        const int qr = tid >> 1, qc = (tid & 1) * 32;
#pragma unroll
        for (int i = 0; i < 8; i++)
            cp16(&Qs[qr * 68 + qc + i * 4], &Qh[(size_t)(row0 + qr) * DEP + qc + i * 4]);
    }
    asm volatile("cp.async.commit_group;" ::: "memory");
    // Prologue group B: K0 / V0
#pragma unroll
    for (int i = 0; i < 4; i++) {
        cp16(&Kb0[kvr * 68 + kvc + i * 4], &Kh[(size_t)kvr * DEP + kvc + i * 4]);
        cp16(&Vb0[kvr * 72 + kvc + i * 4], &Vh[(size_t)kvr * DEP + kvc + i * 4]);
    }
    asm volatile("cp.async.commit_group;" ::: "memory");

    // Wait for Q (group A), extract Q fragments (own-warp rows only)
    asm volatile("cp.async.wait_group 1;" ::: "memory");
    __syncthreads();
    unsigned qa[8][4];
    {
        const int rq = w * 16;
#pragma unroll
        for (int ks = 0; ks < 8; ks++) {
            const int kk = ks * 8;
            qa[ks][0] = Qs[(rq + g) * 68 + kk + t];
            qa[ks][1] = Qs[(rq + g + 8) * 68 + kk + t];
            qa[ks][2] = Qs[(rq + g) * 68 + kk + t + 4];
            qa[ks][3] = Qs[(rq + g + 8) * 68 + kk + t + 4];
        }
    }

    float ctx[8][4];
#pragma unroll
    for (int nt = 0; nt < 8; nt++)
#pragma unroll
        for (int c = 0; c < 4; c++) ctx[nt][c] = 0.f;
    float rs0 = 0.f, rs1 = 0.f;

    const int gi0 = row0 + w * 16 + g;
    const int gi1 = gi0 + 8;
    const int ctmax = 2 * rt + 1;

    for (int ct = 0; ct <= ctmax; ct++) {
        // Prefetch next tile into alternate buffer
        if (ct < ctmax) {
            unsigned* Kn = ((ct + 1) & 1) ? Kb1 : Kb0;
            unsigned* Vn = ((ct + 1) & 1) ? Vb1 : Vb0;
            const size_t gj = (size_t)((ct + 1) * 64 + kvr) * DEP + kvc;
#pragma unroll
            for (int i = 0; i < 4; i++) {
                cp16(&Kn[kvr * 68 + kvc + i * 4], &Kh[gj + i * 4]);
                cp16(&Vn[kvr * 72 + kvc + i * 4], &Vh[gj + i * 4]);
            }
            asm volatile("cp.async.commit_group;" ::: "memory");
            asm volatile("cp.async.wait_group 1;" ::: "memory");
        } else {
            asm volatile("cp.async.wait_group 0;" ::: "memory");
        }
        __syncthreads();

        const unsigned* Ks = (ct & 1) ? Kb1 : Kb0;
        const unsigned* Vs = (ct & 1) ? Vb1 : Vb0;

        // GEMM1: S = Q K^T (warp 16 x 64); K is [j][d]
        float s[8][4];
#pragma unroll
        for (int nt = 0; nt < 8; nt++)
#pragma unroll
            for (int c = 0; c < 4; c++) s[nt][c] = 0.f;
#pragma unroll
        for (int ks = 0; ks < 8; ks++) {
            const int kk = ks * 8;
#pragma unroll
            for (int nt = 0; nt < 8; nt++) {
                unsigned b[2];
                b[0] = Ks[(nt * 8 + g) * 68 + kk + t];
                b[1] = Ks[(nt * 8 + g) * 68 + kk + t + 4];
                mma_tf32(s[nt], qa[ks], b);
            }
        }

        // exp + causal mask; write unnormalized P; stage tf32(P) in Ps (=Qs)
        unsigned* Ps = Qs;
#pragma unroll
        for (int nt = 0; nt < 8; nt++) {
            const int cj = ct * 64 + nt * 8 + 2 * t;
            float e00 = (cj     <= gi0) ? __expf(s[nt][0] * 0.125f) : 0.f;
            float e01 = (cj + 1 <= gi0) ? __expf(s[nt][1] * 0.125f) : 0.f;
            float e10 = (cj     <= gi1) ? __expf(s[nt][2] * 0.125f) : 0.f;
            float e11 = (cj + 1 <= gi1) ? __expf(s[nt][3] * 0.125f) : 0.f;
            rs0 += e00 + e01;
            rs1 += e10 + e11;
            if (write_attn) {
                float2 p0 = make_float2(e00, e01);
                float2 p1 = make_float2(e10, e11);
                *(float2*)&attn_out[((size_t)bh * SS_ + gi0) * SS_ + cj] = p0;
                *(float2*)&attn_out[((size_t)bh * SS_ + gi1) * SS_ + cj] = p1;
            }
            uint2 u0, u1;
            u0.x = f2tf(e00); u0.y = f2tf(e01);
            u1.x = f2tf(e10); u1.y = f2tf(e11);
            *(uint2*)&Ps[(w * 16 + g) * 68 + nt * 8 + 2 * t] = u0;
            *(uint2*)&Ps[(w * 16 + g + 8) * 68 + nt * 8 + 2 * t] = u1;
        }
        __syncwarp();

        // GEMM2: ctx += P V; V is [j][d]
#pragma unroll
        for (int js = 0; js < 8; js++) {
            const int jj = js * 8;
            unsigned pa[4];
            pa[0] = Ps[(w * 16 + g) * 68 + jj + t];
            pa[1] = Ps[(w * 16 + g + 8) * 68 + jj + t];
            pa[2] = Ps[(w * 16 + g) * 68 + jj + t + 4];
            pa[3] = Ps[(w * 16 + g + 8) * 68 + jj + t + 4];
#pragma unroll
            for (int nt = 0; nt < 8; nt++) {
                unsigned b[2];
                b[0] = Vs[(jj + t) * 72 + nt * 8 + g];
                b[1] = Vs[(jj + t + 4) * 72 + nt * 8 + g];
                mma_tf32(ctx[nt], pa, b);
            }
        }
        __syncthreads();  // all warps done with Ks/Vs before cp.async overwrites
    }

    // Row sums -> inv
    rs0 += __shfl_xor_sync(0xffffffffu, rs0, 1);
    rs0 += __shfl_xor_sync(0xffffffffu, rs0, 2);
    rs1 += __shfl_xor_sync(0xffffffffu, rs1, 1);
    rs1 += __shfl_xor_sync(0xffffffffu, rs1, 2);
    const float inv0 = 1.f / rs0, inv1 = 1.f / rs1;
    if (t == 0) {
        g_inv[(size_t)bh * SS_ + gi0] = inv0;
        g_inv[(size_t)bh * SS_ + gi1] = inv1;
    }

    // Store normalized ctx
    const int b = bh >> 3, h = bh & 7;
#pragma unroll
    for (int nt = 0; nt < 8; nt++) {
        const int d = nt * 8 + 2 * t;
        float2 o0, o1;
        o0.x = ctx[nt][0] * inv0; o0.y = ctx[nt][1] * inv0;
        o1.x = ctx[nt][2] * inv1; o1.y = ctx[nt][3] * inv1;
        *(float2*)&g_ctx[((size_t)(b * SS_ + gi0)) * DD + h * 64 + d] = o0;
        *(float2*)&g_ctx[((size_t)(b * SS_ + gi1)) * DD + h * 64 + d] = o1;
    }
}

// ---------------------------------------------------------------------------
// Normalize attn in place; zeros above diagonal (write-only there).
// ---------------------------------------------------------------------------
__global__ void __launch_bounds__(256)
normalize_attn(float* __restrict__ attn) {
    const size_t idx = (size_t)blockIdx.x * 256 + threadIdx.x;  // float4 index
    const int j4 = (int)(idx & 1023);
    const int i  = (int)((idx >> 10) & 4095);
    const int bh = (int)(idx >> 22);
    const int j  = j4 * 4;
    float4* p = (float4*)attn + idx;
    if (j > i) {
        *p = make_float4(0.f, 0.f, 0.f, 0.f);
    } else {
        const float inv = g_inv[(size_t)bh * SS_ + i];
        float4 v = *p;
        if (j + 3 <= i) {
            v.x *= inv; v.y *= inv; v.z *= inv; v.w *= inv;
        } else {
            v.x = (j + 0 <= i) ? v.x * inv : 0.f;
            v.y = (j + 1 <= i) ? v.y * inv : 0.f;
            v.z = (j + 2 <= i) ? v.z * inv : 0.f;
            v.w = (j + 3 <= i) ? v.w * inv : 0.f;
        }
        *p = v;
    }
}

// ---------------------------------------------------------------------------
extern "C" void kernel_launch(void* const* d_in, const int* in_sizes, int n_in,
                              void* d_out, int out_size) {
    const float* q  = (const float*)d_in[2];
    const float* k  = (const float*)d_in[0];
    const float* v  = (const float*)d_in[1];
    const float* Wq = (const float*)d_in[4];
    const float* bq = (const float*)d_in[5];
    const float* Wk = (const float*)d_in[6];
    const float* bk = (const float*)d_in[7];
    const float* Wv = (const float*)d_in[8];
    const float* bv = (const float*)d_in[9];
    const float* Wo = (const float*)d_in[10];
    const float* bo = (const float*)d_in[11];

    float* out = (float*)d_out;
    const size_t BSD = (size_t)BB * SS_ * DD;
    const size_t ATT = (size_t)BH * SS_ * SS_;

    float* out_main = nullptr;
    float* attn_out = nullptr;
    if ((size_t)out_size >= BSD + ATT) {
        out_main = out;
        attn_out = out + BSD;
    } else if ((size_t)out_size >= ATT) {
        attn_out = out;
    } else {
        out_main = out;
    }

    void *pq, *pk, *pv, *pctx;
    cudaGetSymbolAddress(&pq, g_qh);
    cudaGetSymbolAddress(&pk, g_kh);
    cudaGetSymbolAddress(&pv, g_vh);
    cudaGetSymbolAddress(&pctx, g_ctx);

    cudaFuncSetAttribute(attn_kernel,
                         cudaFuncAttributeMaxDynamicSharedMemorySize, 106496);

    dim3 ggrid(4, 64);
    gemm512_mma<1><<<ggrid, 256>>>(q, Wq, bq, (float*)pq);
    gemm512_mma<1><<<ggrid, 256>>>(k, Wk, bk, (float*)pk);
    gemm512_mma<1><<<ggrid, 256>>>(v, Wv, bv, (float*)pv);

    attn_kernel<<<dim3(32, BH), 256, 106496>>>(attn_out, attn_out != nullptr);

    if (attn_out) {
        normalize_attn<<<262144, 256>>>(attn_out);
    }
    if (out_main) {
        gemm512_mma<0><<<ggrid, 256>>>((const float*)pctx, Wo, bo, out_main);
    }
}